// round 1
// baseline (speedup 1.0000x reference)
#include <cuda_runtime.h>
#include <cstdint>

// Gate pipeline:
//   g = conv(inputs, w; stride 4, VALID)  -> [64,1,128,128]
//   per-batch keep top-4096 of 16384, zero the rest
//   out = inputs * upsample4x(broadcast3(g_sparse))
//
// Scratch: per-batch gate map, 64*16384 floats = 4 MB (L2-resident).
__device__ float d_gate[64 * 16384];

// ---------------------------------------------------------------------------
// Kernel 1: 4x4 stride-4 conv, 3->1 channels. One thread per output pixel.
// Each thread: 12 float4 loads (3 channels x 4 rows), dot with weights.
// Warp-contiguous x => each (c,row) load is a fully coalesced 512B segment.
// ---------------------------------------------------------------------------
__global__ void gate_conv_kernel(const float4* __restrict__ in,
                                 const float* __restrict__ wk) {
    __shared__ float4 w[12];
    int t = threadIdx.x;
    if (t < 12) w[t] = reinterpret_cast<const float4*>(wk)[t];
    __syncthreads();

    int idx = blockIdx.x * blockDim.x + t;      // [0, 64*16384)
    int x = idx & 127;                          // gate col
    int y = (idx >> 7) & 127;                   // gate row
    int b = idx >> 14;                          // batch

    // input as float4: per row 128 f4, per channel 65536 f4, per batch 196608 f4
    const float4* base = in + (size_t)b * 196608 + x;

    float sum = 0.0f;
#pragma unroll
    for (int c = 0; c < 3; c++) {
#pragma unroll
        for (int i = 0; i < 4; i++) {
            float4 v = base[c * 65536 + (4 * y + i) * 128];
            float4 ww = w[c * 4 + i];
            sum += v.x * ww.x + v.y * ww.y + v.z * ww.z + v.w * ww.w;
        }
    }
    d_gate[idx] = sum;
}

// ---------------------------------------------------------------------------
// Kernel 2: per-batch exact K-th-largest via MSB-first radix select on
// order-preserving uint keys, then zero all elements strictly below it.
// One block per batch row (16384 elements, K=4096). Data is L2-hot.
// ---------------------------------------------------------------------------
__device__ __forceinline__ unsigned f2key(float f) {
    unsigned u = __float_as_uint(f);
    return (u & 0x80000000u) ? ~u : (u | 0x80000000u);  // monotone map
}

__global__ void gate_select_kernel() {
    __shared__ unsigned hist[256];
    __shared__ unsigned s_prefix;
    __shared__ int s_k;

    const int row = blockIdx.x;
    const int t = threadIdx.x;
    const int bd = blockDim.x;
    float* grow = d_gate + row * 16384;

    if (t == 0) { s_prefix = 0u; s_k = 4096; }
    __syncthreads();

#pragma unroll
    for (int pass = 0; pass < 4; pass++) {
        const int shift = 24 - 8 * pass;
        for (int i = t; i < 256; i += bd) hist[i] = 0u;
        __syncthreads();

        const unsigned pmask = pass ? (0xFFFFFFFFu << (32 - 8 * pass)) : 0u;
        const unsigned prefix = s_prefix;

        for (int i = t; i < 16384; i += bd) {
            unsigned u = f2key(grow[i]);
            if ((u & pmask) == prefix)
                atomicAdd(&hist[(u >> shift) & 0xFFu], 1u);
        }
        __syncthreads();

        if (t == 0) {
            int k = s_k;
            int bin = 255;
            for (;;) {
                int c = (int)hist[bin];
                if (c >= k) break;
                k -= c;
                bin--;
            }
            s_prefix = prefix | ((unsigned)bin << shift);
            s_k = k;
        }
        __syncthreads();
    }

    const unsigned thr = s_prefix;  // exact key of the K-th largest value
    for (int i = t; i < 16384; i += bd) {
        if (f2key(grow[i]) < thr) grow[i] = 0.0f;
    }
}

// ---------------------------------------------------------------------------
// Kernel 3: out = in * gate[b, y/4, x/4], broadcast over channels.
// float4-vectorized: one float4 covers cols 4j..4j+3 => exactly one gate cell.
// ---------------------------------------------------------------------------
__global__ void gate_mul_kernel(const float4* __restrict__ in,
                                float4* __restrict__ out) {
    int idx = blockIdx.x * blockDim.x + threadIdx.x;  // [0, 64*3*512*128)
    int x4 = idx & 127;            // float4 col == gate col
    int y  = (idx >> 7) & 511;     // image row
    int bc = idx >> 16;            // b*3 + c
    int b  = bc / 3;

    float gv = d_gate[b * 16384 + (y >> 2) * 128 + x4];
    float4 v = in[idx];
    v.x *= gv; v.y *= gv; v.z *= gv; v.w *= gv;
    out[idx] = v;
}

// ---------------------------------------------------------------------------
extern "C" void kernel_launch(void* const* d_in, const int* in_sizes, int n_in,
                              void* d_out, int out_size) {
    const float* inp = (const float*)d_in[0];
    const float* wk  = (const float*)d_in[1];
    if (n_in >= 2 && in_sizes[0] == 48) {  // defensive: swap if order flipped
        inp = (const float*)d_in[1];
        wk  = (const float*)d_in[0];
    }

    // 64*16384 gate pixels / 256
    gate_conv_kernel<<<4096, 256>>>((const float4*)inp, wk);
    // one block per batch row
    gate_select_kernel<<<64, 512>>>();
    // 64*3*512*128 float4 / 256
    gate_mul_kernel<<<49152, 256>>>((const float4*)inp, (float4*)d_out);
}